// round 1
// baseline (speedup 1.0000x reference)
#include <cuda_runtime.h>

// KANLayer: out[b,s,o] = sum_{i,n} tanh(h[i,n,o]*x[b,s,i] + b[i,n,o]) * w[i,n,o]
// B=2, S=1024, I=64, N=16, O=64.
// Inputs (metadata order): d_in[0]=x [2,1024,64] f32, d_in[1]=w [64,16,64] f32,
//                          d_in[2]=h [64,16,64] f32, d_in[3]=b [64,16,64] f32.
// Output: f32 [2,1024,64].

#define I_DIM 64
#define N_DIM 16
#define O_DIM 64
#define NROWS 2048            // B*S

#define O_TILE 16             // o-columns per block
#define ROWS_PER_BLOCK 64
#define R_PER_THREAD 4
#define THREADS 256           // 16 o-lanes x 16 row-groups
#define X_PAD 68              // padded row stride for x tile (bank spread)

// shared layout (floats):
//   hb : [I*N][O_TILE][2]  (h,b interleaved)  = 64*16*16*2 = 32768 floats (128KB)
//   ws : [I*N][O_TILE]                         = 16384 floats (64KB)
//   xs : [ROWS_PER_BLOCK][X_PAD]               = 64*68 = 4352 floats (~17KB)
#define HB_FLOATS (I_DIM * N_DIM * O_TILE * 2)
#define WS_FLOATS (I_DIM * N_DIM * O_TILE)
#define XS_FLOATS (ROWS_PER_BLOCK * X_PAD)
#define SMEM_FLOATS (HB_FLOATS + WS_FLOATS + XS_FLOATS)
#define SMEM_BYTES (SMEM_FLOATS * 4)

// tanh(z) = 1 - 2 / (exp(2z) + 1), via MUFU.EX2 + MUFU.RCP.
// Accurate to ~1e-6 relative for all z that contribute meaningfully; saturates
// correctly for |z| large (ex2 -> inf/0).
__device__ __forceinline__ float tanh_fast(float z) {
    float m = z * 2.885390081777927f;   // 2 * log2(e)
    float u;
    asm("ex2.approx.f32 %0, %1;" : "=f"(u) : "f"(m));
    float d = u + 1.0f;
    float r;
    asm("rcp.approx.f32 %0, %1;" : "=f"(r) : "f"(d));
    return fmaf(-2.0f, r, 1.0f);
}

__global__ void __launch_bounds__(THREADS, 1)
kan_kernel(const float* __restrict__ gx, const float* __restrict__ gw,
           const float* __restrict__ gh, const float* __restrict__ gb,
           float* __restrict__ gout) {
    extern __shared__ float smem[];
    float* hb = smem;                      // interleaved (h,b)
    float* ws = smem + HB_FLOATS;
    float* xs = smem + HB_FLOATS + WS_FLOATS;

    const int tid  = threadIdx.x;
    const int o0   = blockIdx.y * O_TILE;
    const int row0 = blockIdx.x * ROWS_PER_BLOCK;

    // ---- stage params for this o-tile ----
    #pragma unroll 4
    for (int idx = tid; idx < I_DIM * N_DIM * O_TILE; idx += THREADS) {
        int ol  = idx & (O_TILE - 1);
        int in_ = idx >> 4;                    // (i*16 + n), since O_TILE == 16
        int g   = in_ * O_DIM + o0 + ol;
        hb[idx * 2 + 0] = gh[g];
        hb[idx * 2 + 1] = gb[g];
        ws[idx]         = gw[g];
    }
    // ---- stage x rows ----
    #pragma unroll 4
    for (int idx = tid; idx < ROWS_PER_BLOCK * I_DIM; idx += THREADS) {
        int r = idx >> 6;                      // I_DIM == 64
        int c = idx & 63;
        xs[r * X_PAD + c] = gx[(row0 + r) * I_DIM + c];
    }
    __syncthreads();

    const int ol  = tid & (O_TILE - 1);
    const int grp = tid >> 4;                  // 0..15, owns 4 rows

    float acc[R_PER_THREAD];
    #pragma unroll
    for (int k = 0; k < R_PER_THREAD; k++) acc[k] = 0.0f;

    const float* xbase = &xs[(grp * R_PER_THREAD) * X_PAD];

    for (int i = 0; i < I_DIM; i++) {
        float xv[R_PER_THREAD];
        #pragma unroll
        for (int k = 0; k < R_PER_THREAD; k++)
            xv[k] = xbase[k * X_PAD + i];

        #pragma unroll 8
        for (int n = 0; n < N_DIM; n++) {
            int e = i * N_DIM + n;
            float2 hb2 = *reinterpret_cast<const float2*>(&hb[(e * O_TILE + ol) * 2]);
            float  wv  = ws[e * O_TILE + ol];
            #pragma unroll
            for (int k = 0; k < R_PER_THREAD; k++) {
                float z = fmaf(hb2.x, xv[k], hb2.y);
                float t = tanh_fast(z);
                acc[k]  = fmaf(t, wv, acc[k]);
            }
        }
    }

    #pragma unroll
    for (int k = 0; k < R_PER_THREAD; k++) {
        int row = row0 + grp * R_PER_THREAD + k;
        gout[row * O_DIM + o0 + ol] = acc[k];
    }
}

extern "C" void kernel_launch(void* const* d_in, const int* in_sizes, int n_in,
                              void* d_out, int out_size) {
    const float* x = (const float*)d_in[0];
    const float* w = (const float*)d_in[1];
    const float* h = (const float*)d_in[2];
    const float* b = (const float*)d_in[3];
    float* out = (float*)d_out;

    cudaFuncSetAttribute(kan_kernel, cudaFuncAttributeMaxDynamicSharedMemorySize,
                         SMEM_BYTES);

    dim3 grid(NROWS / ROWS_PER_BLOCK, O_DIM / O_TILE);   // (32, 4) = 128 blocks
    kan_kernel<<<grid, THREADS, SMEM_BYTES>>>(x, w, h, b, out);
}